// round 3
// baseline (speedup 1.0000x reference)
#include <cuda_runtime.h>
#include <cuda_bf16.h>
#include <math.h>

// Problem constants (fixed shapes in the dataset)
#define DIN   768
#define DOUT  768
#define NB    6          // GRID_NUM + K = 3 + 3
#define NAUG  7          // silu + 6 basis functions
#define KDIM  (NAUG * DIN)   // 5376
#define MAX_NTOK 8192

// Scratch (device-global: no runtime allocation allowed)
__device__ float g_A[(size_t)MAX_NTOK * KDIM];   // augmented activations [N, K]
__device__ float g_W[(size_t)KDIM * DOUT];       // packed weights        [K, Dout]

// ---------------------------------------------------------------------------
// Helpers: extended B-spline grid, grid[t] = (t-3)*(2/3) - 1  (t = 0..9)
// Computed exactly like the JAX reference (float32 arithmetic).
// ---------------------------------------------------------------------------
__device__ __forceinline__ float gridv(int t) {
    return (float)(t - 3) * 0.66666668653488159f /* fp32(2/3) */ - 1.0f;
}

// ---------------------------------------------------------------------------
// Kernel 1: pack weights  W[k*DOUT + o],  k = j*DIN + i
//   j==0 : scale_base[o,i]
//   j>=1 : scale_sp[o,i] * coef[o,i,j-1]
// ---------------------------------------------------------------------------
__global__ void pack_w_kernel(const float* __restrict__ coef,
                              const float* __restrict__ scale_base,
                              const float* __restrict__ scale_sp) {
    long long idx = (long long)blockIdx.x * blockDim.x + threadIdx.x;
    const long long total = (long long)KDIM * DOUT;
    if (idx >= total) return;
    int o = (int)(idx % DOUT);
    int k = (int)(idx / DOUT);
    int j = k / DIN;
    int i = k % DIN;
    float w;
    if (j == 0) {
        w = scale_base[(size_t)o * DIN + i];
    } else {
        w = scale_sp[(size_t)o * DIN + i] * coef[((size_t)o * DIN + i) * NB + (j - 1)];
    }
    g_W[idx] = w;
}

// ---------------------------------------------------------------------------
// Kernel 2: build augmented activations.
// Thread per (n, i).  A[n*K + j*DIN + i] = { silu(x), basis_0..basis_5 }
// Cox-de Boor recursion matching the reference exactly (fp32).
// ---------------------------------------------------------------------------
__global__ void build_a_kernel(const float* __restrict__ x, int ntok) {
    long long idx = (long long)blockIdx.x * blockDim.x + threadIdx.x;
    long long total = (long long)ntok * DIN;
    if (idx >= total) return;

    float xv = x[idx];
    int n = (int)(idx / DIN);
    int i = (int)(idx % DIN);

    // degree-0 indicators over 9 intervals
    float b[9];
#pragma unroll
    for (int t = 0; t < 9; t++) {
        b[t] = (xv >= gridv(t) && xv < gridv(t + 1)) ? 1.0f : 0.0f;
    }
    // Cox-de Boor p = 1..3
#pragma unroll
    for (int p = 1; p <= 3; p++) {
#pragma unroll
        for (int t = 0; t < 8; t++) {
            if (t < 9 - p) {
                float gl  = gridv(t);
                float glp = gridv(t + p);
                float g1  = gridv(t + 1);
                float grp = gridv(t + p + 1);
                float left  = (xv - gl)  / (glp - gl);
                float right = (grp - xv) / (grp - g1);
                b[t] = left * b[t] + right * b[t + 1];
            }
        }
    }
    // silu
    float s = xv / (1.0f + expf(-xv));

    size_t base = (size_t)n * KDIM + i;
    g_A[base] = s;
#pragma unroll
    for (int j = 0; j < NB; j++) {
        g_A[base + (size_t)(j + 1) * DIN] = b[j];
    }
}

// ---------------------------------------------------------------------------
// Kernel 3: SGEMM  C[M, DOUT] = A[M, K] * W[K, DOUT] + bias
// 128x128 tile, BK=16, 256 threads, 8x8 microtile, f32x2 packed FMA
// (fma.rn.f32x2 doubles fp32 throughput vs scalar FFMA on sm_103a).
// ---------------------------------------------------------------------------
#define BM 128
#define BN 128
#define BK 16
#define TM 8
#define TN 8

__device__ __forceinline__ unsigned long long pack2(float lo, float hi) {
    unsigned long long r;
    asm("mov.b64 %0, {%1, %2};" : "=l"(r) : "f"(lo), "f"(hi));
    return r;
}
__device__ __forceinline__ void unpack2(unsigned long long v, float& lo, float& hi) {
    asm("mov.b64 {%0, %1}, %2;" : "=f"(lo), "=f"(hi) : "l"(v));
}
__device__ __forceinline__ void fma2(unsigned long long& d,
                                     unsigned long long a,
                                     unsigned long long b) {
    asm("fma.rn.f32x2 %0, %1, %2, %0;" : "+l"(d) : "l"(a), "l"(b));
}

__global__ __launch_bounds__(256, 2)
void gemm_kernel(const float* __restrict__ A, const float* __restrict__ B,
                 const float* __restrict__ bias, float* __restrict__ C,
                 int M) {
    __shared__ float As[BK][BM + 4];
    __shared__ float Bs[BK][BN];

    const int tid = threadIdx.x;
    const int bm = blockIdx.y * BM;
    const int bn = blockIdx.x * BN;

    const int tr = tid >> 4;            // 0..15
    const int tc = tid & 15;            // 0..15
    const int row0 = tr * TM;
    const int col0 = tc * TN;

    // A tile load mapping: 2 x float4 per thread
    const int a_row = tid >> 2;         // 0..63
    const int a_k   = (tid & 3) * 4;    // 0,4,8,12
    // B tile load mapping: 2 x float4 per thread
    const int b_row = tid >> 5;         // 0..7
    const int b_col = (tid & 31) * 4;   // 0..124

    unsigned long long acc[TM][TN / 2];
#pragma unroll
    for (int r = 0; r < TM; r++)
#pragma unroll
        for (int c = 0; c < TN / 2; c++) acc[r][c] = 0ull;

    for (int k0 = 0; k0 < KDIM; k0 += BK) {
        // --- load A tile (transposed into smem) ---
#pragma unroll
        for (int s = 0; s < 2; s++) {
            int r = a_row + s * 64;
            int grow = bm + r;
            float4 v = make_float4(0.f, 0.f, 0.f, 0.f);
            if (grow < M)
                v = *reinterpret_cast<const float4*>(&A[(size_t)grow * KDIM + k0 + a_k]);
            As[a_k + 0][r] = v.x;
            As[a_k + 1][r] = v.y;
            As[a_k + 2][r] = v.z;
            As[a_k + 3][r] = v.w;
        }
        // --- load B tile ---
#pragma unroll
        for (int s = 0; s < 2; s++) {
            int r = b_row + s * 8;
            *reinterpret_cast<float4*>(&Bs[r][b_col]) =
                *reinterpret_cast<const float4*>(&B[(size_t)(k0 + r) * DOUT + bn + b_col]);
        }
        __syncthreads();

#pragma unroll
        for (int kk = 0; kk < BK; kk++) {
            float4 a0 = *reinterpret_cast<const float4*>(&As[kk][row0]);
            float4 a1 = *reinterpret_cast<const float4*>(&As[kk][row0 + 4]);
            float4 b0 = *reinterpret_cast<const float4*>(&Bs[kk][col0]);
            float4 b1 = *reinterpret_cast<const float4*>(&Bs[kk][col0 + 4]);
            unsigned long long bp[4];
            bp[0] = pack2(b0.x, b0.y);
            bp[1] = pack2(b0.z, b0.w);
            bp[2] = pack2(b1.x, b1.y);
            bp[3] = pack2(b1.z, b1.w);
            float av[TM] = {a0.x, a0.y, a0.z, a0.w, a1.x, a1.y, a1.z, a1.w};
#pragma unroll
            for (int r = 0; r < TM; r++) {
                unsigned long long ad = pack2(av[r], av[r]);
#pragma unroll
                for (int c = 0; c < TN / 2; c++) fma2(acc[r][c], ad, bp[c]);
            }
        }
        __syncthreads();
    }

    // --- epilogue: add bias, store ---
    float bv[TN];
#pragma unroll
    for (int c = 0; c < TN; c++) bv[c] = bias[bn + col0 + c];

#pragma unroll
    for (int r = 0; r < TM; r++) {
        int grow = bm + row0 + r;
        if (grow < M) {
            float o[TN];
#pragma unroll
            for (int c = 0; c < TN / 2; c++)
                unpack2(acc[r][c], o[2 * c], o[2 * c + 1]);
            float4 v0 = make_float4(o[0] + bv[0], o[1] + bv[1], o[2] + bv[2], o[3] + bv[3]);
            float4 v1 = make_float4(o[4] + bv[4], o[5] + bv[5], o[6] + bv[6], o[7] + bv[7]);
            float* cp = &C[(size_t)grow * DOUT + bn + col0];
            *reinterpret_cast<float4*>(cp)     = v0;
            *reinterpret_cast<float4*>(cp + 4) = v1;
        }
    }
}

// ---------------------------------------------------------------------------
// Launch
// inputs (metadata order): x, coef, scale_base, scale_sp, bias
// ---------------------------------------------------------------------------
extern "C" void kernel_launch(void* const* d_in, const int* in_sizes, int n_in,
                              void* d_out, int out_size) {
    const float* x          = (const float*)d_in[0];
    const float* coef       = (const float*)d_in[1];
    const float* scale_base = (const float*)d_in[2];
    const float* scale_sp   = (const float*)d_in[3];
    const float* bias       = (const float*)d_in[4];
    float* out = (float*)d_out;

    int ntok = in_sizes[0] / DIN;              // 8192
    if (ntok > MAX_NTOK) ntok = MAX_NTOK;

    float* A;
    float* W;
    cudaGetSymbolAddress((void**)&A, g_A);
    cudaGetSymbolAddress((void**)&W, g_W);

    // 1) pack weights
    {
        long long total = (long long)KDIM * DOUT;
        int threads = 256;
        int blocks = (int)((total + threads - 1) / threads);
        pack_w_kernel<<<blocks, threads>>>(coef, scale_base, scale_sp);
    }
    // 2) build augmented activations
    {
        long long total = (long long)ntok * DIN;
        int threads = 256;
        int blocks = (int)((total + threads - 1) / threads);
        build_a_kernel<<<blocks, threads>>>(x, ntok);
    }
    // 3) GEMM
    {
        dim3 grid(DOUT / BN, (ntok + BM - 1) / BM);   // (6, 64)
        gemm_kernel<<<grid, 256>>>(A, W, bias, out, ntok);
    }
}

// round 5
// speedup vs baseline: 3.0866x; 3.0866x over previous
#include <cuda_runtime.h>
#include <cuda_bf16.h>
#include <math.h>
#include <stdint.h>

// ---------------------------------------------------------------------------
// Problem constants
// ---------------------------------------------------------------------------
#define DIN   768
#define DOUT  768
#define NB    6                  // GRID_NUM + K
#define NAUG  7                  // silu + 6 basis
#define KDIM  (NAUG * DIN)       // 5376
#define KC    64                 // bf16 elements per K-chunk (128 bytes/row)
#define NKC   (KDIM / KC)        // 84 chunks
#define TILE_BYTES 16384         // 128 rows x 128 bytes (SW128 swizzled)
#define MAX_NTOK 8192
#define MT_MAX (MAX_NTOK / 128)  // 64 M tiles
#define NT     (DOUT / 128)      // 6 N tiles

// Pre-swizzled bf16 tile storage (hi / lo splits). Device globals = legal scratch.
__device__ __align__(1024) unsigned char g_Ahi[(size_t)MT_MAX * NKC * TILE_BYTES];
__device__ __align__(1024) unsigned char g_Alo[(size_t)MT_MAX * NKC * TILE_BYTES];
__device__ __align__(1024) unsigned char g_Whi[(size_t)NT * NKC * TILE_BYTES];
__device__ __align__(1024) unsigned char g_Wlo[(size_t)NT * NKC * TILE_BYTES];

#define SWZ(o) ((o) ^ ((((uint32_t)(o)) >> 3) & 0x70u))

// ---------------------------------------------------------------------------
// PTX helpers — all family-agnostic (sm_90 / sm_80 features, NO 'a'-specific)
// ---------------------------------------------------------------------------
__device__ __forceinline__ uint32_t smem_u32(const void* p) {
    uint32_t a;
    asm("{ .reg .u64 t; cvta.to.shared.u64 t, %1; cvt.u32.u64 %0, t; }" : "=r"(a) : "l"(p));
    return a;
}

#define MBARRIER_INIT(addr, cnt) \
    asm volatile("mbarrier.init.shared.b64 [%0], %1;" :: "r"(addr), "r"(cnt) : "memory")

#define MBARRIER_EXPECT_TX(addr, bytes) \
    asm volatile("mbarrier.arrive.expect_tx.shared.b64 _, [%0], %1;" :: "r"(addr), "r"(bytes) : "memory")

__device__ __forceinline__ void mbar_wait_parity(uint32_t mbar, uint32_t parity) {
    uint32_t done;
    asm volatile(
        "{ .reg .pred p; mbarrier.try_wait.parity.acquire.cta.shared::cta.b64 p, [%1], %2; selp.b32 %0, 1, 0, p; }"
        : "=r"(done) : "r"(mbar), "r"(parity) : "memory");
    if (!done) {
        asm volatile(
            "{ .reg .pred P1;\n"
            "WL_%=: mbarrier.try_wait.parity.acquire.cta.shared::cta.b64 P1, [%0], %1, 0x989680;\n"
            "@P1 bra.uni WD_%=;\n"
            "bra.uni WL_%=;\n"
            "WD_%=: }\n"
            :: "r"(mbar), "r"(parity) : "memory");
    }
}

__device__ __forceinline__ void bulk_copy_g2s(uint32_t dst, const void* src,
                                              uint32_t bytes, uint32_t mbar) {
    asm volatile(
        "cp.async.bulk.shared::cluster.global.mbarrier::complete_tx::bytes [%0], [%1], %2, [%3];"
        :: "r"(dst), "l"(src), "r"(bytes), "r"(mbar) : "memory");
}

#define FENCE_PROXY_ASYNC() asm volatile("fence.proxy.async.shared::cta;" ::: "memory")

__device__ __forceinline__ void ldmatrix_x4(uint32_t& r0, uint32_t& r1,
                                            uint32_t& r2, uint32_t& r3, uint32_t addr) {
    asm volatile("ldmatrix.sync.aligned.m8n8.x4.shared.b16 {%0,%1,%2,%3}, [%4];"
                 : "=r"(r0), "=r"(r1), "=r"(r2), "=r"(r3) : "r"(addr));
}

__device__ __forceinline__ void mma_16816(float* c, const uint32_t* a,
                                          uint32_t b0, uint32_t b1) {
    asm volatile(
        "mma.sync.aligned.m16n8k16.row.col.f32.bf16.bf16.f32 "
        "{%0,%1,%2,%3}, {%4,%5,%6,%7}, {%8,%9}, {%0,%1,%2,%3};"
        : "+f"(c[0]), "+f"(c[1]), "+f"(c[2]), "+f"(c[3])
        : "r"(a[0]), "r"(a[1]), "r"(a[2]), "r"(a[3]), "r"(b0), "r"(b1));
}

// ---------------------------------------------------------------------------
// B-spline helpers (fp32, identical to reference arithmetic)
// ---------------------------------------------------------------------------
__device__ __forceinline__ float gridv(int t) {
    return (float)(t - 3) * 0.66666668653488159f - 1.0f;
}

__device__ __forceinline__ void bspline6(float xv, float* out6) {
    float b[9];
#pragma unroll
    for (int t = 0; t < 9; t++)
        b[t] = (xv >= gridv(t) && xv < gridv(t + 1)) ? 1.0f : 0.0f;
#pragma unroll
    for (int p = 1; p <= 3; p++) {
#pragma unroll
        for (int t = 0; t < 8; t++) {
            if (t < 9 - p) {
                float gl = gridv(t), glp = gridv(t + p);
                float g1 = gridv(t + 1), grp = gridv(t + p + 1);
                float left  = (xv - gl)  / (glp - gl);
                float right = (grp - xv) / (grp - g1);
                b[t] = left * b[t] + right * b[t + 1];
            }
        }
    }
#pragma unroll
    for (int j = 0; j < 6; j++) out6[j] = b[j];
}

union Pack8 {
    uint4 q;
    unsigned short s[8];
};

__device__ __forceinline__ void split_store(float v, Pack8& hi, Pack8& lo, int slot) {
    __nv_bfloat16 h = __float2bfloat16_rn(v);
    float rem = v - __bfloat162float(h);
    __nv_bfloat16 l = __float2bfloat16_rn(rem);
    hi.s[slot] = __bfloat16_as_ushort(h);
    lo.s[slot] = __bfloat16_as_ushort(l);
}

// ---------------------------------------------------------------------------
// Kernel 1: build augmented A (silu | basis) as pre-swizzled bf16 hi/lo tiles
// ---------------------------------------------------------------------------
__global__ void build_a_kernel(const float* __restrict__ x, int ntok, int mtiles) {
    int idx = blockIdx.x * blockDim.x + threadIdx.x;
    int total = mtiles * 128 * 96;
    if (idx >= total) return;
    int n  = idx / 96;
    int i8 = idx % 96;
    int mt = n >> 7, r = n & 127;

    float xv[8];
    if (n < ntok) {
        const float4* xp = (const float4*)(x + (size_t)n * DIN + i8 * 8);
        float4 v0 = xp[0], v1 = xp[1];
        xv[0] = v0.x; xv[1] = v0.y; xv[2] = v0.z; xv[3] = v0.w;
        xv[4] = v1.x; xv[5] = v1.y; xv[6] = v1.z; xv[7] = v1.w;
    } else {
#pragma unroll
        for (int v = 0; v < 8; v++) xv[v] = 0.0f;
    }

    float vals[NAUG][8];
#pragma unroll
    for (int v = 0; v < 8; v++) {
        float xs = xv[v];
        if (n < ntok) {
            vals[0][v] = xs / (1.0f + expf(-xs));
            float b6[6];
            bspline6(xs, b6);
#pragma unroll
            for (int j = 0; j < 6; j++) vals[j + 1][v] = b6[j];
        } else {
#pragma unroll
            for (int j = 0; j < NAUG; j++) vals[j][v] = 0.0f;
        }
    }

#pragma unroll
    for (int j = 0; j < NAUG; j++) {
        int k  = j * DIN + i8 * 8;
        int kc = k >> 6;
        int cb = k & 63;
        size_t tb = ((size_t)(mt * NKC + kc)) << 14;
        uint32_t off = SWZ((uint32_t)(r * 128 + cb * 2));
        Pack8 hi, lo;
#pragma unroll
        for (int v = 0; v < 8; v++) split_store(vals[j][v], hi, lo, v);
        *(uint4*)(g_Ahi + tb + off) = hi.q;
        *(uint4*)(g_Alo + tb + off) = lo.q;
    }
}

// ---------------------------------------------------------------------------
// Kernel 2: pack W (scale_base | scale_sp*coef) as pre-swizzled bf16 hi/lo tiles
// ---------------------------------------------------------------------------
__global__ void pack_w_kernel(const float* __restrict__ coef,
                              const float* __restrict__ sb,
                              const float* __restrict__ ss) {
    int idx = blockIdx.x * blockDim.x + threadIdx.x;
    const int total = DOUT * (KDIM / 8);
    if (idx >= total) return;
    int o  = idx / (KDIM / 8);
    int k8 = idx % (KDIM / 8);
    int j  = k8 / 96;
    int ib = (k8 % 96) * 8;

    float vals[8];
    if (j == 0) {
#pragma unroll
        for (int v = 0; v < 8; v++) vals[v] = sb[(size_t)o * DIN + ib + v];
    } else {
#pragma unroll
        for (int v = 0; v < 8; v++) {
            size_t e = (size_t)o * DIN + ib + v;
            vals[v] = ss[e] * coef[e * NB + (j - 1)];
        }
    }

    int ntile = o >> 7, r = o & 127;
    int kc = k8 >> 3;
    int cb = (k8 & 7) * 8;
    size_t tb = ((size_t)(ntile * NKC + kc)) << 14;
    uint32_t off = SWZ((uint32_t)(r * 128 + cb * 2));
    Pack8 hi, lo;
#pragma unroll
    for (int v = 0; v < 8; v++) split_store(vals[v], hi, lo, v);
    *(uint4*)(g_Whi + tb + off) = hi.q;
    *(uint4*)(g_Wlo + tb + off) = lo.q;
}

// ---------------------------------------------------------------------------
// Kernel 3: mma.sync bf16x3 GEMM
// CTA 128x128, 256 threads (8 warps, 2(M) x 4(N)), warp tile 64x32.
// Double-buffered cp.async.bulk pipeline (stage = Ahi|Alo|Bhi|Blo = 64 KB).
// ---------------------------------------------------------------------------
#define STAGE_BYTES 65536u

__global__ __launch_bounds__(256, 1)
void gemm_kernel(const float* __restrict__ bias, float* __restrict__ out, int ntok) {
    extern __shared__ __align__(16) unsigned char smem[];
    uint32_t sbase = smem_u32(smem);
    uint32_t tiles = (sbase + 32 + 127) & ~127u;

    const int tid  = threadIdx.x;
    const int wid  = tid >> 5;
    const int lane = tid & 31;
    const int bn = blockIdx.x;            // 0..5
    const int bm = blockIdx.y;            // 0..mtiles-1
    const int wm = wid & 1;               // 0..1  (M)
    const int wn = wid >> 1;              // 0..3  (N)

    const uint32_t full0 = sbase, full1 = sbase + 16;

    if (tid == 0) {
        MBARRIER_INIT(full0, 1);
        MBARRIER_INIT(full1, 1);
        FENCE_PROXY_ASYNC();
    }
    __syncthreads();

    const unsigned char* Ah = g_Ahi + (((size_t)bm * NKC) << 14);
    const unsigned char* Al = g_Alo + (((size_t)bm * NKC) << 14);
    const unsigned char* Wh = g_Whi + (((size_t)bn * NKC) << 14);
    const unsigned char* Wl = g_Wlo + (((size_t)bn * NKC) << 14);

    // Prologue: prefetch chunks 0 and 1
    if (tid == 0) {
#pragma unroll
        for (int c = 0; c < 2; c++) {
            uint32_t fb = c ? full1 : full0;
            uint32_t t = tiles + c * STAGE_BYTES;
            MBARRIER_EXPECT_TX(fb, STAGE_BYTES);
            bulk_copy_g2s(t,          Ah + ((size_t)c << 14), 16384, fb);
            bulk_copy_g2s(t + 16384,  Al + ((size_t)c << 14), 16384, fb);
            bulk_copy_g2s(t + 32768,  Wh + ((size_t)c << 14), 16384, fb);
            bulk_copy_g2s(t + 49152,  Wl + ((size_t)c << 14), 16384, fb);
        }
    }

    // ldmatrix lane address offsets (within a 16 KB tile)
    // A: m16xk16 block: lanes 0-15 -> rows m0-15 (k+0), lanes 16-31 -> rows m0-15 (k+16B)
    const int a_row = wm * 64 + (lane & 15);
    const int a_kb  = (lane >> 4) * 16;
    // B: n16xk16 block: r0:n0-7 k0, r1:n0-7 k8, r2:n8-15 k0, r3:n8-15 k8
    const int b_row = wn * 32 + ((lane >> 4) << 3) + (lane & 7);
    const int b_kb  = ((lane >> 3) & 1) * 16;

    float acc[4][4][4];
#pragma unroll
    for (int i = 0; i < 4; i++)
#pragma unroll
        for (int j = 0; j < 4; j++)
#pragma unroll
            for (int q = 0; q < 4; q++) acc[i][j][q] = 0.0f;

    for (int c = 0; c < NKC; c++) {
        int stage = c & 1;
        uint32_t fb = stage ? full1 : full0;
        mbar_wait_parity(fb, (uint32_t)((c >> 1) & 1));

        uint32_t t  = tiles + stage * STAGE_BYTES;
        uint32_t tAh = t, tAl = t + 16384, tBh = t + 32768, tBl = t + 49152;

#pragma unroll
        for (int kk = 0; kk < 4; kk++) {
            uint32_t afh[4][4], afl[4][4];
            uint32_t bfh[2][4], bfl[2][4];
#pragma unroll
            for (int mb = 0; mb < 4; mb++) {
                uint32_t off = SWZ((uint32_t)((a_row + mb * 16) * 128 + kk * 32 + a_kb));
                ldmatrix_x4(afh[mb][0], afh[mb][1], afh[mb][2], afh[mb][3], tAh + off);
                ldmatrix_x4(afl[mb][0], afl[mb][1], afl[mb][2], afl[mb][3], tAl + off);
            }
#pragma unroll
            for (int np = 0; np < 2; np++) {
                uint32_t off = SWZ((uint32_t)((b_row + np * 16) * 128 + kk * 32 + b_kb));
                ldmatrix_x4(bfh[np][0], bfh[np][1], bfh[np][2], bfh[np][3], tBh + off);
                ldmatrix_x4(bfl[np][0], bfl[np][1], bfl[np][2], bfl[np][3], tBl + off);
            }
#pragma unroll
            for (int mb = 0; mb < 4; mb++) {
#pragma unroll
                for (int nb = 0; nb < 4; nb++) {
                    int np = nb >> 1, h = (nb & 1) * 2;
                    // hi*hi + hi*lo + lo*hi
                    mma_16816(acc[mb][nb], afh[mb], bfh[np][h], bfh[np][h + 1]);
                    mma_16816(acc[mb][nb], afh[mb], bfl[np][h], bfl[np][h + 1]);
                    mma_16816(acc[mb][nb], afl[mb], bfh[np][h], bfh[np][h + 1]);
                }
            }
        }

        __syncthreads();   // everyone done reading this stage
        if (tid == 0 && c + 2 < NKC) {
            int nc = c + 2;
            MBARRIER_EXPECT_TX(fb, STAGE_BYTES);
            bulk_copy_g2s(t,          Ah + ((size_t)nc << 14), 16384, fb);
            bulk_copy_g2s(t + 16384,  Al + ((size_t)nc << 14), 16384, fb);
            bulk_copy_g2s(t + 32768,  Wh + ((size_t)nc << 14), 16384, fb);
            bulk_copy_g2s(t + 49152,  Wl + ((size_t)nc << 14), 16384, fb);
        }
    }

    // ---- epilogue: add bias, store ----
    const int col_base = bn * 128 + wn * 32;
    const int row_base = bm * 128 + wm * 64 + (lane >> 2);
    const int csub = (lane & 3) * 2;

    float bv[4][2];
#pragma unroll
    for (int nb = 0; nb < 4; nb++) {
        bv[nb][0] = __ldg(&bias[col_base + nb * 8 + csub]);
        bv[nb][1] = __ldg(&bias[col_base + nb * 8 + csub + 1]);
    }

#pragma unroll
    for (int mb = 0; mb < 4; mb++) {
#pragma unroll
        for (int half = 0; half < 2; half++) {
            int row = row_base + mb * 16 + half * 8;
            if (row < ntok) {
                float* op = out + (size_t)row * DOUT + col_base + csub;
#pragma unroll
                for (int nb = 0; nb < 4; nb++) {
                    float2 w;
                    w.x = acc[mb][nb][half * 2 + 0] + bv[nb][0];
                    w.y = acc[mb][nb][half * 2 + 1] + bv[nb][1];
                    *(float2*)(op + nb * 8) = w;
                }
            }
        }
    }
}

// ---------------------------------------------------------------------------
// Launch — inputs: x, coef, scale_base, scale_sp, bias
// ---------------------------------------------------------------------------
extern "C" void kernel_launch(void* const* d_in, const int* in_sizes, int n_in,
                              void* d_out, int out_size) {
    const float* x          = (const float*)d_in[0];
    const float* coef       = (const float*)d_in[1];
    const float* scale_base = (const float*)d_in[2];
    const float* scale_sp   = (const float*)d_in[3];
    const float* bias       = (const float*)d_in[4];
    float* out = (float*)d_out;

    int ntok = in_sizes[0] / DIN;
    if (ntok > MAX_NTOK) ntok = MAX_NTOK;
    int mtiles = (ntok + 127) / 128;

    // 1) pack W hi/lo tiles
    {
        int total = DOUT * (KDIM / 8);
        pack_w_kernel<<<(total + 255) / 256, 256>>>(coef, scale_base, scale_sp);
    }
    // 2) build A hi/lo tiles
    {
        int total = mtiles * 128 * 96;
        build_a_kernel<<<(total + 255) / 256, 256>>>(x, ntok, mtiles);
    }
    // 3) tensor-core GEMM (mma.sync bf16x3)
    {
        const int smem_req = 2 * 65536 + 256;   // 2 stages + barrier header
        cudaFuncSetAttribute(gemm_kernel, cudaFuncAttributeMaxDynamicSharedMemorySize, smem_req);
        dim3 grid(NT, mtiles);
        gemm_kernel<<<grid, 256, smem_req>>>(bias, out, ntok);
    }
}

// round 6
// speedup vs baseline: 3.1984x; 1.0362x over previous
#include <cuda_runtime.h>
#include <cuda_bf16.h>
#include <math.h>
#include <stdint.h>

// ---------------------------------------------------------------------------
// Problem constants
// ---------------------------------------------------------------------------
#define DIN   768
#define DOUT  768
#define NB    6                  // GRID_NUM + K
#define NAUG  7                  // silu + 6 basis
#define KDIM  (NAUG * DIN)       // 5376
#define KC    64                 // bf16 elements per K-chunk (128 bytes/row)
#define NKC   (KDIM / KC)        // 84 chunks
#define NSPLIT 3                 // split-K factor
#define NKC_SPLIT (NKC / NSPLIT) // 28 chunks per split
#define TILE_BYTES 16384         // 128 rows x 128 bytes (SW128 swizzled)
#define MAX_NTOK 8192
#define MT_MAX (MAX_NTOK / 128)  // 64 M tiles
#define NT     (DOUT / 128)      // 6 N tiles

// Pre-swizzled bf16 tile storage (hi / lo splits) + split-K partials.
__device__ __align__(1024) unsigned char g_Ahi[(size_t)MT_MAX * NKC * TILE_BYTES];
__device__ __align__(1024) unsigned char g_Alo[(size_t)MT_MAX * NKC * TILE_BYTES];
__device__ __align__(1024) unsigned char g_Whi[(size_t)NT * NKC * TILE_BYTES];
__device__ __align__(1024) unsigned char g_Wlo[(size_t)NT * NKC * TILE_BYTES];
__device__ __align__(16)   float g_part[NSPLIT][(size_t)MAX_NTOK * DOUT];

#define SWZ(o) ((o) ^ ((((uint32_t)(o)) >> 3) & 0x70u))

// ---------------------------------------------------------------------------
// PTX helpers — all family-agnostic (sm_90 / sm_80 features, NO 'a'-specific)
// ---------------------------------------------------------------------------
__device__ __forceinline__ uint32_t smem_u32(const void* p) {
    uint32_t a;
    asm("{ .reg .u64 t; cvta.to.shared.u64 t, %1; cvt.u32.u64 %0, t; }" : "=r"(a) : "l"(p));
    return a;
}

#define MBARRIER_INIT(addr, cnt) \
    asm volatile("mbarrier.init.shared.b64 [%0], %1;" :: "r"(addr), "r"(cnt) : "memory")

#define MBARRIER_EXPECT_TX(addr, bytes) \
    asm volatile("mbarrier.arrive.expect_tx.shared.b64 _, [%0], %1;" :: "r"(addr), "r"(bytes) : "memory")

__device__ __forceinline__ void mbar_wait_parity(uint32_t mbar, uint32_t parity) {
    uint32_t done;
    asm volatile(
        "{ .reg .pred p; mbarrier.try_wait.parity.acquire.cta.shared::cta.b64 p, [%1], %2; selp.b32 %0, 1, 0, p; }"
        : "=r"(done) : "r"(mbar), "r"(parity) : "memory");
    if (!done) {
        asm volatile(
            "{ .reg .pred P1;\n"
            "WL_%=: mbarrier.try_wait.parity.acquire.cta.shared::cta.b64 P1, [%0], %1, 0x989680;\n"
            "@P1 bra.uni WD_%=;\n"
            "bra.uni WL_%=;\n"
            "WD_%=: }\n"
            :: "r"(mbar), "r"(parity) : "memory");
    }
}

__device__ __forceinline__ void bulk_copy_g2s(uint32_t dst, const void* src,
                                              uint32_t bytes, uint32_t mbar) {
    asm volatile(
        "cp.async.bulk.shared::cluster.global.mbarrier::complete_tx::bytes [%0], [%1], %2, [%3];"
        :: "r"(dst), "l"(src), "r"(bytes), "r"(mbar) : "memory");
}

#define FENCE_PROXY_ASYNC() asm volatile("fence.proxy.async.shared::cta;" ::: "memory")

__device__ __forceinline__ void ldmatrix_x4(uint32_t& r0, uint32_t& r1,
                                            uint32_t& r2, uint32_t& r3, uint32_t addr) {
    asm volatile("ldmatrix.sync.aligned.m8n8.x4.shared.b16 {%0,%1,%2,%3}, [%4];"
                 : "=r"(r0), "=r"(r1), "=r"(r2), "=r"(r3) : "r"(addr));
}

__device__ __forceinline__ void mma_16816(float* c, const uint32_t* a,
                                          uint32_t b0, uint32_t b1) {
    asm volatile(
        "mma.sync.aligned.m16n8k16.row.col.f32.bf16.bf16.f32 "
        "{%0,%1,%2,%3}, {%4,%5,%6,%7}, {%8,%9}, {%0,%1,%2,%3};"
        : "+f"(c[0]), "+f"(c[1]), "+f"(c[2]), "+f"(c[3])
        : "r"(a[0]), "r"(a[1]), "r"(a[2]), "r"(a[3]), "r"(b0), "r"(b1));
}

// ---------------------------------------------------------------------------
// B-spline helpers (fp32, identical to reference arithmetic)
// ---------------------------------------------------------------------------
__device__ __forceinline__ float gridv(int t) {
    return (float)(t - 3) * 0.66666668653488159f - 1.0f;
}

__device__ __forceinline__ void bspline6(float xv, float* out6) {
    float b[9];
#pragma unroll
    for (int t = 0; t < 9; t++)
        b[t] = (xv >= gridv(t) && xv < gridv(t + 1)) ? 1.0f : 0.0f;
#pragma unroll
    for (int p = 1; p <= 3; p++) {
#pragma unroll
        for (int t = 0; t < 8; t++) {
            if (t < 9 - p) {
                float gl = gridv(t), glp = gridv(t + p);
                float g1 = gridv(t + 1), grp = gridv(t + p + 1);
                float left  = (xv - gl)  / (glp - gl);
                float right = (grp - xv) / (grp - g1);
                b[t] = left * b[t] + right * b[t + 1];
            }
        }
    }
#pragma unroll
    for (int j = 0; j < 6; j++) out6[j] = b[j];
}

union Pack8 {
    uint4 q;
    unsigned short s[8];
};

__device__ __forceinline__ void split_store(float v, Pack8& hi, Pack8& lo, int slot) {
    __nv_bfloat16 h = __float2bfloat16_rn(v);
    float rem = v - __bfloat162float(h);
    __nv_bfloat16 l = __float2bfloat16_rn(rem);
    hi.s[slot] = __bfloat16_as_ushort(h);
    lo.s[slot] = __bfloat16_as_ushort(l);
}

// ---------------------------------------------------------------------------
// Kernel 1: pack W (scale_base | scale_sp*coef) as pre-swizzled bf16 hi/lo tiles
// ---------------------------------------------------------------------------
__global__ void pack_w_kernel(const float* __restrict__ coef,
                              const float* __restrict__ sb,
                              const float* __restrict__ ss) {
    int idx = blockIdx.x * blockDim.x + threadIdx.x;
    const int total = DOUT * (KDIM / 8);
    if (idx >= total) return;
    int o  = idx / (KDIM / 8);
    int k8 = idx % (KDIM / 8);
    int j  = k8 / 96;
    int ib = (k8 % 96) * 8;

    float vals[8];
    if (j == 0) {
#pragma unroll
        for (int v = 0; v < 8; v++) vals[v] = sb[(size_t)o * DIN + ib + v];
    } else {
#pragma unroll
        for (int v = 0; v < 8; v++) {
            size_t e = (size_t)o * DIN + ib + v;
            vals[v] = ss[e] * coef[e * NB + (j - 1)];
        }
    }

    int ntile = o >> 7, r = o & 127;
    int kc = k8 >> 3;
    int cb = (k8 & 7) * 8;
    size_t tb = ((size_t)(ntile * NKC + kc)) << 14;
    uint32_t off = SWZ((uint32_t)(r * 128 + cb * 2));
    Pack8 hi, lo;
#pragma unroll
    for (int v = 0; v < 8; v++) split_store(vals[v], hi, lo, v);
    *(uint4*)(g_Whi + tb + off) = hi.q;
    *(uint4*)(g_Wlo + tb + off) = lo.q;
}

// ---------------------------------------------------------------------------
// Kernel 2: build augmented A (silu | basis) as pre-swizzled bf16 hi/lo tiles
// ---------------------------------------------------------------------------
__global__ void build_a_kernel(const float* __restrict__ x, int ntok, int mtiles) {
    int idx = blockIdx.x * blockDim.x + threadIdx.x;
    int total = mtiles * 128 * 96;
    if (idx >= total) return;
    int n  = idx / 96;
    int i8 = idx % 96;
    int mt = n >> 7, r = n & 127;

    float xv[8];
    if (n < ntok) {
        const float4* xp = (const float4*)(x + (size_t)n * DIN + i8 * 8);
        float4 v0 = xp[0], v1 = xp[1];
        xv[0] = v0.x; xv[1] = v0.y; xv[2] = v0.z; xv[3] = v0.w;
        xv[4] = v1.x; xv[5] = v1.y; xv[6] = v1.z; xv[7] = v1.w;
    } else {
#pragma unroll
        for (int v = 0; v < 8; v++) xv[v] = 0.0f;
    }

    float vals[NAUG][8];
#pragma unroll
    for (int v = 0; v < 8; v++) {
        float xs = xv[v];
        if (n < ntok) {
            vals[0][v] = xs / (1.0f + expf(-xs));
            float b6[6];
            bspline6(xs, b6);
#pragma unroll
            for (int j = 0; j < 6; j++) vals[j + 1][v] = b6[j];
        } else {
#pragma unroll
            for (int j = 0; j < NAUG; j++) vals[j][v] = 0.0f;
        }
    }

#pragma unroll
    for (int j = 0; j < NAUG; j++) {
        int k  = j * DIN + i8 * 8;
        int kc = k >> 6;
        int cb = k & 63;
        size_t tb = ((size_t)(mt * NKC + kc)) << 14;
        uint32_t off = SWZ((uint32_t)(r * 128 + cb * 2));
        Pack8 hi, lo;
#pragma unroll
        for (int v = 0; v < 8; v++) split_store(vals[j][v], hi, lo, v);
        *(uint4*)(g_Ahi + tb + off) = hi.q;
        *(uint4*)(g_Alo + tb + off) = lo.q;
    }
}

// ---------------------------------------------------------------------------
// Kernel 3: mma.sync bf16x3 GEMM, split-K x3.
// CTA 128x128, 256 threads (8 warps, 2(M) x 4(N)), warp tile 64x32.
// 3-stage cp.async.bulk pipeline (stage = Ahi|Alo|Bhi|Blo = 64 KB).
// blockIdx.z = K split; writes fp32 partials (no bias).
// ---------------------------------------------------------------------------
#define STAGE_BYTES 65536u
#define NSTG 3

__global__ __launch_bounds__(256, 1)
void gemm_kernel(int ntok) {
    extern __shared__ __align__(16) unsigned char smem[];
    uint32_t sbase = smem_u32(smem);
    uint32_t tiles = (sbase + 64 + 1023) & ~1023u;

    const int tid  = threadIdx.x;
    const int wid  = tid >> 5;
    const int lane = tid & 31;
    const int bn = blockIdx.x;            // 0..5
    const int bm = blockIdx.y;            // 0..mtiles-1
    const int ks = blockIdx.z;            // 0..2 split-K
    const int wm = wid & 1;               // 0..1  (M)
    const int wn = wid >> 1;              // 0..3  (N)

    const uint32_t fb0 = sbase, fb1 = sbase + 16, fb2 = sbase + 32;

    if (tid == 0) {
        MBARRIER_INIT(fb0, 1);
        MBARRIER_INIT(fb1, 1);
        MBARRIER_INIT(fb2, 1);
        FENCE_PROXY_ASYNC();
    }
    __syncthreads();

    const int c0 = ks * NKC_SPLIT;   // first chunk of this split
    const unsigned char* Ah = g_Ahi + (((size_t)(bm * NKC + c0)) << 14);
    const unsigned char* Al = g_Alo + (((size_t)(bm * NKC + c0)) << 14);
    const unsigned char* Wh = g_Whi + (((size_t)(bn * NKC + c0)) << 14);
    const unsigned char* Wl = g_Wlo + (((size_t)(bn * NKC + c0)) << 14);

    // Prologue: prefetch chunks 0..2 into stages 0..2
    if (tid == 0) {
#pragma unroll
        for (int c = 0; c < NSTG; c++) {
            uint32_t fb = sbase + 16 * c;
            uint32_t t = tiles + c * STAGE_BYTES;
            MBARRIER_EXPECT_TX(fb, STAGE_BYTES);
            bulk_copy_g2s(t,          Ah + ((size_t)c << 14), 16384, fb);
            bulk_copy_g2s(t + 16384,  Al + ((size_t)c << 14), 16384, fb);
            bulk_copy_g2s(t + 32768,  Wh + ((size_t)c << 14), 16384, fb);
            bulk_copy_g2s(t + 49152,  Wl + ((size_t)c << 14), 16384, fb);
        }
    }

    // ldmatrix lane address offsets (within a 16 KB tile)
    const int a_row = wm * 64 + (lane & 15);
    const int a_kb  = (lane >> 4) * 16;
    const int b_row = wn * 32 + ((lane >> 4) << 3) + (lane & 7);
    const int b_kb  = ((lane >> 3) & 1) * 16;

    float acc[4][4][4];
#pragma unroll
    for (int i = 0; i < 4; i++)
#pragma unroll
        for (int j = 0; j < 4; j++)
#pragma unroll
            for (int q = 0; q < 4; q++) acc[i][j][q] = 0.0f;

    for (int c = 0; c < NKC_SPLIT; c++) {
        int stage = c % NSTG;
        uint32_t fb = sbase + 16 * stage;
        mbar_wait_parity(fb, (uint32_t)((c / NSTG) & 1));

        uint32_t t  = tiles + stage * STAGE_BYTES;
        uint32_t tAh = t, tAl = t + 16384, tBh = t + 32768, tBl = t + 49152;

#pragma unroll
        for (int kk = 0; kk < 4; kk++) {
            uint32_t afh[4][4], afl[4][4];
            uint32_t bfh[2][4], bfl[2][4];
#pragma unroll
            for (int mb = 0; mb < 4; mb++) {
                uint32_t off = SWZ((uint32_t)((a_row + mb * 16) * 128 + kk * 32 + a_kb));
                ldmatrix_x4(afh[mb][0], afh[mb][1], afh[mb][2], afh[mb][3], tAh + off);
                ldmatrix_x4(afl[mb][0], afl[mb][1], afl[mb][2], afl[mb][3], tAl + off);
            }
#pragma unroll
            for (int np = 0; np < 2; np++) {
                uint32_t off = SWZ((uint32_t)((b_row + np * 16) * 128 + kk * 32 + b_kb));
                ldmatrix_x4(bfh[np][0], bfh[np][1], bfh[np][2], bfh[np][3], tBh + off);
                ldmatrix_x4(bfl[np][0], bfl[np][1], bfl[np][2], bfl[np][3], tBl + off);
            }
#pragma unroll
            for (int mb = 0; mb < 4; mb++) {
#pragma unroll
                for (int nb = 0; nb < 4; nb++) {
                    int np = nb >> 1, h = (nb & 1) * 2;
                    mma_16816(acc[mb][nb], afh[mb], bfh[np][h], bfh[np][h + 1]);
                    mma_16816(acc[mb][nb], afh[mb], bfl[np][h], bfl[np][h + 1]);
                    mma_16816(acc[mb][nb], afl[mb], bfh[np][h], bfh[np][h + 1]);
                }
            }
        }

        __syncthreads();   // all warps done reading stage `stage`
        if (tid == 0 && c + NSTG < NKC_SPLIT) {
            int nc = c + NSTG;
            MBARRIER_EXPECT_TX(fb, STAGE_BYTES);
            bulk_copy_g2s(t,          Ah + ((size_t)nc << 14), 16384, fb);
            bulk_copy_g2s(t + 16384,  Al + ((size_t)nc << 14), 16384, fb);
            bulk_copy_g2s(t + 32768,  Wh + ((size_t)nc << 14), 16384, fb);
            bulk_copy_g2s(t + 49152,  Wl + ((size_t)nc << 14), 16384, fb);
        }
    }

    // ---- epilogue: store fp32 partials ----
    float* part = g_part[ks];
    const int col_base = bn * 128 + wn * 32;
    const int row_base = bm * 128 + wm * 64 + (lane >> 2);
    const int csub = (lane & 3) * 2;

#pragma unroll
    for (int mb = 0; mb < 4; mb++) {
#pragma unroll
        for (int half = 0; half < 2; half++) {
            int row = row_base + mb * 16 + half * 8;
            if (row < ntok) {
                float* op = part + (size_t)row * DOUT + col_base + csub;
#pragma unroll
                for (int nb = 0; nb < 4; nb++) {
                    float2 w;
                    w.x = acc[mb][nb][half * 2 + 0];
                    w.y = acc[mb][nb][half * 2 + 1];
                    *(float2*)(op + nb * 8) = w;
                }
            }
        }
    }
}

// ---------------------------------------------------------------------------
// Kernel 4: reduce split-K partials + bias -> out
// ---------------------------------------------------------------------------
__global__ void reduce_kernel(const float* __restrict__ bias,
                              float* __restrict__ out, int total4) {
    int idx = blockIdx.x * blockDim.x + threadIdx.x;
    if (idx >= total4) return;
    float4 p0 = ((const float4*)g_part[0])[idx];
    float4 p1 = ((const float4*)g_part[1])[idx];
    float4 p2 = ((const float4*)g_part[2])[idx];
    int col = (idx * 4) % DOUT;
    float4 b = *(const float4*)(bias + col);
    float4 w;
    w.x = p0.x + p1.x + p2.x + b.x;
    w.y = p0.y + p1.y + p2.y + b.y;
    w.z = p0.z + p1.z + p2.z + b.z;
    w.w = p0.w + p1.w + p2.w + b.w;
    ((float4*)out)[idx] = w;
}

// ---------------------------------------------------------------------------
// Launch — inputs: x, coef, scale_base, scale_sp, bias
// ---------------------------------------------------------------------------
extern "C" void kernel_launch(void* const* d_in, const int* in_sizes, int n_in,
                              void* d_out, int out_size) {
    const float* x          = (const float*)d_in[0];
    const float* coef       = (const float*)d_in[1];
    const float* scale_base = (const float*)d_in[2];
    const float* scale_sp   = (const float*)d_in[3];
    const float* bias       = (const float*)d_in[4];
    float* out = (float*)d_out;

    int ntok = in_sizes[0] / DIN;
    if (ntok > MAX_NTOK) ntok = MAX_NTOK;
    int mtiles = (ntok + 127) / 128;

    // 1) pack W hi/lo tiles
    {
        int total = DOUT * (KDIM / 8);
        pack_w_kernel<<<(total + 255) / 256, 256>>>(coef, scale_base, scale_sp);
    }
    // 2) build A hi/lo tiles
    {
        int total = mtiles * 128 * 96;
        build_a_kernel<<<(total + 255) / 256, 256>>>(x, ntok, mtiles);
    }
    // 3) tensor-core GEMM (mma.sync bf16x3, split-K x3, 3-stage pipe)
    {
        const int smem_req = NSTG * 65536 + 1152;
        cudaFuncSetAttribute(gemm_kernel, cudaFuncAttributeMaxDynamicSharedMemorySize, smem_req);
        dim3 grid(NT, mtiles, NSPLIT);
        gemm_kernel<<<grid, 256, smem_req>>>(ntok);
    }
    // 4) reduce partials + bias
    {
        int total4 = ntok * DOUT / 4;
        reduce_kernel<<<(total4 + 255) / 256, 256>>>(bias, out, total4);
    }
}